// round 1
// baseline (speedup 1.0000x reference)
#include <cuda_runtime.h>

// ThreeBodyLayer_82635170775664 — warp-per-row fused baseline.
//
// Factorized layer 1: cp = core@W1c, A_k = lig_k@W1a, B_k = lig_k@W1b.
// Per ordered pair (i,j): h1 = sp(cp + A_i + B_j); t = h1@W2 + b2;
// y += sp(t)@W3.  out = 0.5 * sum_{i != j} y + 15*b3.
//
// Layout: one warp owns one batch row at a time. 64-dim vectors live
// lane-distributed as (v[lane], v[lane+32]). x broadcast via __shfl_sync.
// W1a/W1b staged in SMEM as float4 (wa_lo, wa_hi, wb_lo, wb_hi) per (d,lane):
// one LDS.128 feeds 4 FMAs. W2 staged in SMEM [64][32]. Core-projection
// weights (only 64 of 832 outputs) read straight from global (L1-resident,
// 16 KB) to keep dynamic SMEM at 40 KB (< 48 KB => no cudaFuncSetAttribute
// inside graph capture). Unordered pairs computed both-orders-together so
// each W2 LDS feeds two combos.

#define FULLMASK 0xFFFFFFFFu

__device__ __forceinline__ float softplus_f(float x) {
    // numerically stable: max(x,0) + log(1 + exp(-|x|)); MUFU EX2/LG2 path
    return fmaxf(x, 0.0f) + __logf(1.0f + __expf(-fabsf(x)));
}

__global__ void __launch_bounds__(256) three_body_kernel(
    const float* __restrict__ core,   // [B, 64]
    const float* __restrict__ ligs,   // [B, 6, 64]
    const float* __restrict__ W1,     // [192, 64]
    const float* __restrict__ b1,     // [64]
    const float* __restrict__ W2,     // [64, 32]
    const float* __restrict__ b2,     // [32]
    const float* __restrict__ W3,     // [32]
    const float* __restrict__ b3,     // [1]
    float* __restrict__ out,          // [B]
    int B)
{
    extern __shared__ unsigned char smem_raw[];
    float4* s_ab = reinterpret_cast<float4*>(smem_raw);          // [64][32] float4, 32 KB
    float*  s_w2 = reinterpret_cast<float*>(smem_raw + 32768);   // [64][32] float,   8 KB

    // Stage lig-projection weights (rows 64..191 of W1) and W2.
    for (int idx = threadIdx.x; idx < 2048; idx += 256) {
        int d = idx >> 5;        // 0..63 : x-element index within a lig vector
        int l = idx & 31;        // lane
        s_ab[idx] = make_float4(W1[(64  + d) * 64 + l],
                                W1[(64  + d) * 64 + l + 32],
                                W1[(128 + d) * 64 + l],
                                W1[(128 + d) * 64 + l + 32]);
        s_w2[idx] = W2[idx];
    }
    __syncthreads();

    const int lane = threadIdx.x & 31;
    const int gw   = (blockIdx.x * 256 + threadIdx.x) >> 5;
    const int nw   = (gridDim.x * 256) >> 5;

    const float b1a = b1[lane];
    const float b1b = b1[lane + 32];
    const float b2l = b2[lane];
    const float w3l = W3[lane];
    const float b3v = b3[0];

    for (int r = gw; r < B; r += nw) {
        const float* crow = core + (size_t)r * 64;
        const float* lrow = ligs + (size_t)r * 384;

        float c0 = crow[lane];
        float c1 = crow[lane + 32];
        float la[6], lb[6];
        #pragma unroll
        for (int k = 0; k < 6; k++) {
            la[k] = lrow[k * 64 + lane];
            lb[k] = lrow[k * 64 + 32 + lane];
        }

        // ---- core projection: cp = core @ W1[0:64] + b1 (weights via L1) ----
        float cp0 = b1a, cp1 = b1b;
        #pragma unroll 8
        for (int d = 0; d < 32; d++) {
            float bc = __shfl_sync(FULLMASK, c0, d);
            cp0 = fmaf(bc, __ldg(&W1[d * 64 + lane]),      cp0);
            cp1 = fmaf(bc, __ldg(&W1[d * 64 + lane + 32]), cp1);
        }
        #pragma unroll 8
        for (int d = 0; d < 32; d++) {
            float bc = __shfl_sync(FULLMASK, c1, d);
            cp0 = fmaf(bc, __ldg(&W1[(d + 32) * 64 + lane]),      cp0);
            cp1 = fmaf(bc, __ldg(&W1[(d + 32) * 64 + lane + 32]), cp1);
        }

        // ---- lig projections: A_k = lig_k @ W1a, B_k = lig_k @ W1b ----
        float A0[6], A1[6], B0[6], B1[6];
        #pragma unroll
        for (int k = 0; k < 6; k++) {
            float a0 = 0.f, a1 = 0.f, q0 = 0.f, q1 = 0.f;
            #pragma unroll 8
            for (int d = 0; d < 32; d++) {
                float  bc = __shfl_sync(FULLMASK, la[k], d);
                float4 w  = s_ab[d * 32 + lane];
                a0 = fmaf(bc, w.x, a0);  a1 = fmaf(bc, w.y, a1);
                q0 = fmaf(bc, w.z, q0);  q1 = fmaf(bc, w.w, q1);
            }
            #pragma unroll 8
            for (int d = 0; d < 32; d++) {
                float  bc = __shfl_sync(FULLMASK, lb[k], d);
                float4 w  = s_ab[(d + 32) * 32 + lane];
                a0 = fmaf(bc, w.x, a0);  a1 = fmaf(bc, w.y, a1);
                q0 = fmaf(bc, w.z, q0);  q1 = fmaf(bc, w.w, q1);
            }
            A0[k] = a0; A1[k] = a1; B0[k] = q0; B1[k] = q1;
        }

        // ---- pair loop: both orders of each unordered pair share W2 loads ----
        float acc = 0.0f;
        #pragma unroll
        for (int i = 0; i < 6; i++) {
            #pragma unroll
            for (int j = i + 1; j < 6; j++) {
                float ha0 = softplus_f(cp0 + A0[i] + B0[j]);
                float ha1 = softplus_f(cp1 + A1[i] + B1[j]);
                float hb0 = softplus_f(cp0 + A0[j] + B0[i]);
                float hb1 = softplus_f(cp1 + A1[j] + B1[i]);

                float taA = b2l, taB = 0.f;   // split accumulators: shorter FMA chains
                float tbA = b2l, tbB = 0.f;
                #pragma unroll 8
                for (int d = 0; d < 32; d++) {
                    float w = s_w2[d * 32 + lane];
                    taA = fmaf(__shfl_sync(FULLMASK, ha0, d), w, taA);
                    tbA = fmaf(__shfl_sync(FULLMASK, hb0, d), w, tbA);
                }
                #pragma unroll 8
                for (int d = 0; d < 32; d++) {
                    float w = s_w2[(d + 32) * 32 + lane];
                    taB = fmaf(__shfl_sync(FULLMASK, ha1, d), w, taB);
                    tbB = fmaf(__shfl_sync(FULLMASK, hb1, d), w, tbB);
                }
                acc += (softplus_f(taA + taB) + softplus_f(tbA + tbB)) * w3l;
            }
        }

        // ---- reduce over the 32 W3 columns and write ----
        #pragma unroll
        for (int off = 16; off; off >>= 1)
            acc += __shfl_xor_sync(FULLMASK, acc, off);
        if (lane == 0)
            out[r] = 0.5f * acc + 15.0f * b3v;
    }
}

extern "C" void kernel_launch(void* const* d_in, const int* in_sizes, int n_in,
                              void* d_out, int out_size) {
    const float* core = (const float*)d_in[0];
    const float* ligs = (const float*)d_in[1];
    const float* W1   = (const float*)d_in[2];
    const float* b1   = (const float*)d_in[3];
    const float* W2   = (const float*)d_in[4];
    const float* b2   = (const float*)d_in[5];
    const float* W3   = (const float*)d_in[6];
    const float* b3   = (const float*)d_in[7];
    float* out = (float*)d_out;

    const int B = in_sizes[0] / 64;           // 32768
    const int smem_bytes = 32768 + 8192;      // 40 KB (< 48 KB, no attribute needed)

    three_body_kernel<<<1024, 256, smem_bytes>>>(
        core, ligs, W1, b1, W2, b2, W3, b3, out, B);
}

// round 2
// speedup vs baseline: 2.3703x; 2.3703x over previous
#include <cuda_runtime.h>

// ThreeBodyLayer — round 2: shfl-free, f32x2-packed, warp-per-row.
//
// Factorized layer 1: cp = core@W1c + b1, A_k = lig_k@W1a, B_k = lig_k@W1b,
// CA_k = cp + A_k.  Per ordered pair (i,j): h1 = sp(CA_i + B_j);
// t = h1@W2 + b2; y += sp(t)·W3[m].  out = 0.5·Σy + 15·b3.
//
// Warp owns a row. 64-dim vectors packed as f32x2 {v[lane], v[lane+32]}.
// x broadcasts via broadcast-LDS from an SMEM-staged x row (no SHFL).
// Lig-projection weights read once per d and shared by all 6 ligands
// (12 packed FMAs per LDS.128). Layer-2 weights: lane m holds W2[:,m]
// as 32 f32x2 registers; h1 round-trips through SMEM (4 STS.32 +
// 16 broadcast LDS.128 per ordered pair). All GEMV math is fma.rn.f32x2.

typedef unsigned long long ull;

#define FULLMASK 0xFFFFFFFFu

__device__ __forceinline__ ull pk(float lo, float hi) {
    ull r; asm("mov.b64 %0, {%1, %2};" : "=l"(r) : "f"(lo), "f"(hi)); return r;
}
__device__ __forceinline__ void upk(ull v, float& lo, float& hi) {
    asm("mov.b64 {%0, %1}, %2;" : "=f"(lo), "=f"(hi) : "l"(v));
}
__device__ __forceinline__ ull fma2(ull a, ull b, ull c) {
    ull d; asm("fma.rn.f32x2 %0, %1, %2, %3;" : "=l"(d) : "l"(a), "l"(b), "l"(c)); return d;
}
__device__ __forceinline__ ull add2(ull a, ull b) {
    ull d; asm("add.rn.f32x2 %0, %1, %2;" : "=l"(d) : "l"(a), "l"(b)); return d;
}

__device__ __forceinline__ float softplus_f(float x) {
    return fmaxf(x, 0.0f) + __logf(1.0f + __expf(-fabsf(x)));
}

// ---- dynamic SMEM layout ----
// [0,      16384)  ull        s_wc[64*32]   core-proj weights, packed pairs
// [16384,  49152)  ulonglong2 s_ab[64*32]   {wa_pack, wb_pack} per (d,lane)
// [49152,  64000)  float      s_x [8][464]  staged x row per warp (448 used)
// [64000,  72192)  float      s_h1[8][256]  h1 double buffer per warp
static constexpr int SMEM_BYTES = 72192;

__global__ void __launch_bounds__(256, 2) three_body_kernel(
    const float* __restrict__ core,   // [B, 64]
    const float* __restrict__ ligs,   // [B, 6, 64]
    const float* __restrict__ W1,     // [192, 64]
    const float* __restrict__ b1,     // [64]
    const float* __restrict__ W2,     // [64, 32]
    const float* __restrict__ b2,     // [32]
    const float* __restrict__ W3,     // [32]
    const float* __restrict__ b3,     // [1]
    float* __restrict__ out,          // [B]
    int B)
{
    extern __shared__ unsigned char sm[];
    ull*        s_wc = reinterpret_cast<ull*>(sm);
    ulonglong2* s_ab = reinterpret_cast<ulonglong2*>(sm + 16384);
    float*      s_x  = reinterpret_cast<float*>(sm + 49152);
    float*      s_h1 = reinterpret_cast<float*>(sm + 64000);

    // ---- stage weights (block-wide, once) ----
    for (int idx = threadIdx.x; idx < 2048; idx += 256) {
        int d = idx >> 5, l = idx & 31;
        s_wc[idx] = pk(W1[d * 64 + l], W1[d * 64 + l + 32]);
        ulonglong2 v;
        v.x = pk(W1[(64  + d) * 64 + l], W1[(64  + d) * 64 + l + 32]);
        v.y = pk(W1[(128 + d) * 64 + l], W1[(128 + d) * 64 + l + 32]);
        s_ab[idx] = v;
    }
    __syncthreads();

    const int lane = threadIdx.x & 31;
    const int warp = threadIdx.x >> 5;
    const int gw   = (blockIdx.x * 256 + threadIdx.x) >> 5;
    const int nw   = (gridDim.x * 256) >> 5;

    // ---- W2 column for lane m, packed over d-pairs (persistent registers) ----
    ull w2q[32];
    #pragma unroll
    for (int dp = 0; dp < 32; dp++)
        w2q[dp] = pk(W2[(2 * dp) * 32 + lane], W2[(2 * dp + 1) * 32 + lane]);

    const float b1a = b1[lane];
    const float b1b = b1[lane + 32];
    const float b2l = b2[lane];
    const float w3l = W3[lane];
    const float b3v = b3[0];

    float* xw = s_x  + warp * 464;   // 448 floats used, 16B-aligned stride
    float* hw = s_h1 + warp * 256;   // two 128-float buffers

    for (int r = gw; r < B; r += nw) {
        // ---- stage x row: core(64) + ligs(384) as 112 float4 ----
        __syncwarp();
        {
            const float4* c4 = reinterpret_cast<const float4*>(core + (size_t)r * 64);
            const float4* l4 = reinterpret_cast<const float4*>(ligs + (size_t)r * 384);
            float4* x4 = reinterpret_cast<float4*>(xw);
            if (lane < 16) x4[lane] = c4[lane];
            #pragma unroll
            for (int t = 0; t < 3; t++) x4[16 + t * 32 + lane] = l4[t * 32 + lane];
        }
        __syncwarp();

        // ---- core projection: cp = core@W1c + b1 (packed halves) ----
        ull cpA = pk(b1a, b1b), cpB = pk(0.0f, 0.0f);
        {
            const float4* x4 = reinterpret_cast<const float4*>(xw);
            #pragma unroll
            for (int t = 0; t < 16; t++) {
                float4 q = x4[t];                          // broadcast LDS.128
                cpA = fma2(pk(q.x, q.x), s_wc[(4 * t + 0) * 32 + lane], cpA);
                cpB = fma2(pk(q.y, q.y), s_wc[(4 * t + 1) * 32 + lane], cpB);
                cpA = fma2(pk(q.z, q.z), s_wc[(4 * t + 2) * 32 + lane], cpA);
                cpB = fma2(pk(q.w, q.w), s_wc[(4 * t + 3) * 32 + lane], cpB);
            }
        }
        const ull cp = add2(cpA, cpB);

        // ---- lig projections, weight-amortized: one LDS.128 feeds 12 FMAs ----
        ull accA[6], accB[6];
        #pragma unroll
        for (int k = 0; k < 6; k++) { accA[k] = pk(0.f, 0.f); accB[k] = pk(0.f, 0.f); }
        #pragma unroll 8
        for (int d = 0; d < 64; d++) {
            ulonglong2 w = s_ab[d * 32 + lane];            // {wa_pack, wb_pack}
            #pragma unroll
            for (int k = 0; k < 6; k++) {
                float xv = xw[64 + k * 64 + d];            // broadcast LDS.32
                ull xx = pk(xv, xv);
                accA[k] = fma2(xx, w.x, accA[k]);
                accB[k] = fma2(xx, w.y, accB[k]);
            }
        }
        ull CA[6], BB[6];
        #pragma unroll
        for (int k = 0; k < 6; k++) { CA[k] = add2(cp, accA[k]); BB[k] = accB[k]; }

        // ---- pair loop: h1 via SMEM broadcast, W2 in registers ----
        float accRow = 0.0f;
        int parity = 0;
        #pragma unroll
        for (int i = 0; i < 6; i++) {
            #pragma unroll
            for (int j = i + 1; j < 6; j++) {
                float* hb = hw + parity * 128; parity ^= 1;
                {
                    float sa0, sa1, sb0, sb1;
                    upk(add2(CA[i], BB[j]), sa0, sa1);
                    upk(add2(CA[j], BB[i]), sb0, sb1);
                    hb[lane]      = softplus_f(sa0);
                    hb[lane + 32] = softplus_f(sa1);
                    hb[lane + 64] = softplus_f(sb0);
                    hb[lane + 96] = softplus_f(sb1);
                }
                __syncwarp();
                const float4* h4 = reinterpret_cast<const float4*>(hb);

                ull tA = pk(0.f, 0.f), tB = pk(0.f, 0.f);
                #pragma unroll
                for (int t = 0; t < 16; t++) {
                    float4 q = h4[t];                      // broadcast LDS.128
                    tA = fma2(pk(q.x, q.y), w2q[2 * t],     tA);
                    tB = fma2(pk(q.z, q.w), w2q[2 * t + 1], tB);
                }
                ull uA = pk(0.f, 0.f), uB = pk(0.f, 0.f);
                #pragma unroll
                for (int t = 0; t < 16; t++) {
                    float4 q = h4[16 + t];
                    uA = fma2(pk(q.x, q.y), w2q[2 * t],     uA);
                    uB = fma2(pk(q.z, q.w), w2q[2 * t + 1], uB);
                }
                float p0, p1, q0, q1;
                upk(add2(tA, tB), p0, p1);
                upk(add2(uA, uB), q0, q1);
                accRow += (softplus_f(p0 + p1 + b2l) + softplus_f(q0 + q1 + b2l)) * w3l;
            }
        }

        // ---- reduce over the 32 output-neuron lanes and write ----
        #pragma unroll
        for (int off = 16; off; off >>= 1)
            accRow += __shfl_xor_sync(FULLMASK, accRow, off);
        if (lane == 0)
            out[r] = 0.5f * accRow + 15.0f * b3v;
    }
}

extern "C" void kernel_launch(void* const* d_in, const int* in_sizes, int n_in,
                              void* d_out, int out_size) {
    const float* core = (const float*)d_in[0];
    const float* ligs = (const float*)d_in[1];
    const float* W1   = (const float*)d_in[2];
    const float* b1   = (const float*)d_in[3];
    const float* W2   = (const float*)d_in[4];
    const float* b2   = (const float*)d_in[5];
    const float* W3   = (const float*)d_in[6];
    const float* b3   = (const float*)d_in[7];
    float* out = (float*)d_out;

    const int B = in_sizes[0] / 64;   // 32768

    cudaFuncSetAttribute(three_body_kernel,
                         cudaFuncAttributeMaxDynamicSharedMemorySize, SMEM_BYTES);

    three_body_kernel<<<1024, 256, SMEM_BYTES>>>(
        core, ligs, W1, b1, W2, b2, W3, b3, out, B);
}